// round 2
// baseline (speedup 1.0000x reference)
#include <cuda_runtime.h>
#include <math.h>

#define BB 2
#define TT 4096
#define DD 768
#define HH 12
#define DHD 64
#define MTOT (BB*TT)        // 8192
#define NQKV (3*DD)         // 2304

// Scratch (static device allocations are allowed; cudaMalloc is not).
__device__ float g_q[(size_t)BB*HH*TT*DHD];     // [b*H+h][t][d]
__device__ float g_k[(size_t)BB*HH*TT*DHD];
__device__ float g_v[(size_t)BB*HH*TT*DHD];
__device__ float g_attn[(size_t)MTOT*DD];       // [b*T+t][h*64+d]

// ---------------------------------------------------------------------------
// QKV GEMM: qkv = x @ W_qkv + b_qkv, scattered into g_q/g_k/g_v.
// 64x64 tile, BK=16, 256 threads, 4x4 microtile, reg-double-buffered staging.
// ---------------------------------------------------------------------------
__global__ void __launch_bounds__(256) qkv_gemm_kernel(
    const float* __restrict__ x, const float* __restrict__ W,
    const float* __restrict__ bias)
{
    __shared__ float As[16][68];   // [kk][m] (transposed store)
    __shared__ float Bs[16][68];   // [kk][n]
    const int tid = threadIdx.x;
    const int tx = tid & 15, ty = tid >> 4;
    const int n0 = blockIdx.x * 64;
    const int m0 = blockIdx.y * 64;
    const int ar = tid >> 2, ac4 = tid & 3;     // A loader: 64 rows x 4 float4
    const int br = tid >> 4, bc4 = tid & 15;    // B loader: 16 rows x 16 float4

    float acc[4][4] = {};
    // Prefetch first k-tile into registers.
    float4 av = *(const float4*)&x[(size_t)(m0 + ar) * DD + ac4 * 4];
    float4 bv = *(const float4*)&W[(size_t)br * NQKV + n0 + bc4 * 4];

    for (int k0 = 0; k0 < DD; k0 += 16) {
        __syncthreads();
        As[ac4*4+0][ar] = av.x; As[ac4*4+1][ar] = av.y;
        As[ac4*4+2][ar] = av.z; As[ac4*4+3][ar] = av.w;
        *(float4*)&Bs[br][bc4*4] = bv;
        __syncthreads();
        if (k0 + 16 < DD) {   // prefetch next tile; latency hidden under FMAs
            av = *(const float4*)&x[(size_t)(m0 + ar) * DD + (k0+16) + ac4 * 4];
            bv = *(const float4*)&W[(size_t)(k0+16 + br) * NQKV + n0 + bc4 * 4];
        }
        #pragma unroll
        for (int kk = 0; kk < 16; kk++) {
            float4 af = *(const float4*)&As[kk][ty*4];
            float4 bf = *(const float4*)&Bs[kk][tx*4];
            float a[4] = {af.x, af.y, af.z, af.w};
            float b[4] = {bf.x, bf.y, bf.z, bf.w};
            #pragma unroll
            for (int i = 0; i < 4; i++)
                #pragma unroll
                for (int j = 0; j < 4; j++)
                    acc[i][j] += a[i] * b[j];
        }
    }
    // Epilogue: add bias, scatter to q/k/v in [b*H+h][t][d] layout.
    #pragma unroll
    for (int i = 0; i < 4; i++) {
        int m = m0 + ty*4 + i;
        int b_ = m / TT, t = m - b_ * TT;
        #pragma unroll
        for (int j = 0; j < 4; j++) {
            int n = n0 + tx*4 + j;
            float v = acc[i][j] + bias[n];
            int which = n / DD;
            int rem = n - which * DD;
            int h = rem >> 6;
            int d = rem & 63;
            size_t idx = ((size_t)(b_*HH + h) * TT + t) * DHD + d;
            if (which == 0)      g_q[idx] = v;
            else if (which == 1) g_k[idx] = v;
            else                 g_v[idx] = v;
        }
    }
}

// ---------------------------------------------------------------------------
// Flash attention, causal, fp32. One CTA = 64 queries of one (b,h).
// SMEM: Qs/Ks d-major transposed [d][row] (bcast+contig reads),
//       Vs row-major [k][d], Ps row-major [qrow][k] (bcast reads in PV).
// K/V staging is register double-buffered across k-tiles.
// ---------------------------------------------------------------------------
#define ATTN_SMEM (4 * 64 * 68 * 4)

__global__ void __launch_bounds__(256) attn_kernel()
{
    extern __shared__ float sm[];
    float (*Qs)[68] = (float(*)[68])(sm);
    float (*Ks)[68] = (float(*)[68])(sm + 64*68);
    float (*Vs)[68] = (float(*)[68])(sm + 2*64*68);
    float (*Ps)[68] = (float(*)[68])(sm + 3*64*68);

    const int tid = threadIdx.x;
    const int tx = tid & 15, ty = tid >> 4;
    const int qt = (gridDim.x - 1) - blockIdx.x;   // heavy tiles first
    const int bh = blockIdx.y;
    const float* Qg = g_q + (size_t)bh * TT * DHD;
    const float* Kg = g_k + (size_t)bh * TT * DHD;
    const float* Vg = g_v + (size_t)bh * TT * DHD;
    const float scale = 0.125f;  // 1/sqrt(64)

    const int lr  = tid >> 4;        // loader row base (0..15), +16 per step
    const int lc4 = tid & 15;        // loader col (float4 index)

    // Load Q tile, pre-scaled, transposed to [d][row].
    #pragma unroll
    for (int l = 0; l < 4; l++) {
        int r = lr + l * 16;
        float4 v = *(const float4*)&Qg[(size_t)(qt*64 + r) * DHD + lc4*4];
        Qs[lc4*4+0][r] = v.x * scale; Qs[lc4*4+1][r] = v.y * scale;
        Qs[lc4*4+2][r] = v.z * scale; Qs[lc4*4+3][r] = v.w * scale;
    }

    float m_i[4] = {-INFINITY, -INFINITY, -INFINITY, -INFINITY};
    float l_i[4] = {};
    float o[4][4] = {};

    // Prefetch kt=0 K/V into registers.
    float4 kreg[4], vreg[4];
    #pragma unroll
    for (int l = 0; l < 4; l++) {
        int r = lr + l * 16;
        kreg[l] = *(const float4*)&Kg[(size_t)r * DHD + lc4*4];
        vreg[l] = *(const float4*)&Vg[(size_t)r * DHD + lc4*4];
    }

    for (int kt = 0; kt <= qt; kt++) {
        __syncthreads();   // previous PV done reading Vs/Ps
        #pragma unroll
        for (int l = 0; l < 4; l++) {
            int r = lr + l * 16;
            Ks[lc4*4+0][r] = kreg[l].x; Ks[lc4*4+1][r] = kreg[l].y;
            Ks[lc4*4+2][r] = kreg[l].z; Ks[lc4*4+3][r] = kreg[l].w;
            *(float4*)&Vs[r][lc4*4] = vreg[l];
        }
        __syncthreads();
        if (kt < qt) {     // prefetch next tile; latency hidden under S compute
            #pragma unroll
            for (int l = 0; l < 4; l++) {
                int r = lr + l * 16;
                kreg[l] = *(const float4*)&Kg[(size_t)((kt+1)*64 + r) * DHD + lc4*4];
                vreg[l] = *(const float4*)&Vg[(size_t)((kt+1)*64 + r) * DHD + lc4*4];
            }
        }

        // S = (Q*scale) K^T  (4x4 per thread)
        float s[4][4] = {};
        #pragma unroll 8
        for (int d = 0; d < 64; d++) {
            float4 qf = *(const float4*)&Qs[d][ty*4];
            float4 kf = *(const float4*)&Ks[d][tx*4];
            float a[4] = {qf.x, qf.y, qf.z, qf.w};
            float b[4] = {kf.x, kf.y, kf.z, kf.w};
            #pragma unroll
            for (int i = 0; i < 4; i++)
                #pragma unroll
                for (int j = 0; j < 4; j++)
                    s[i][j] += a[i] * b[j];
        }
        if (kt == qt) {   // diagonal tile: causal mask
            #pragma unroll
            for (int i = 0; i < 4; i++)
                #pragma unroll
                for (int j = 0; j < 4; j++)
                    if (tx*4 + j > ty*4 + i) s[i][j] = -1e30f;
        }

        // Online softmax: row max/sum via 16-lane shuffle groups.
        #pragma unroll
        for (int i = 0; i < 4; i++) {
            float rmax = fmaxf(fmaxf(s[i][0], s[i][1]), fmaxf(s[i][2], s[i][3]));
            #pragma unroll
            for (int msk = 1; msk < 16; msk <<= 1)
                rmax = fmaxf(rmax, __shfl_xor_sync(0xffffffffu, rmax, msk));
            float mnew = fmaxf(m_i[i], rmax);
            float alpha = __expf(m_i[i] - mnew);
            m_i[i] = mnew;
            float rsum = 0.f;
            #pragma unroll
            for (int j = 0; j < 4; j++) {
                float p = __expf(s[i][j] - mnew);
                s[i][j] = p;
                rsum += p;
            }
            #pragma unroll
            for (int msk = 1; msk < 16; msk <<= 1)
                rsum += __shfl_xor_sync(0xffffffffu, rsum, msk);
            l_i[i] = l_i[i] * alpha + rsum;
            #pragma unroll
            for (int j = 0; j < 4; j++) o[i][j] *= alpha;
            #pragma unroll
            for (int j = 0; j < 4; j++) Ps[ty*4 + i][tx*4 + j] = s[i][j];
        }
        __syncthreads();

        // O += P @ V
        #pragma unroll 4
        for (int k = 0; k < 64; k++) {
            float4 vf = *(const float4*)&Vs[k][tx*4];
            float vb[4] = {vf.x, vf.y, vf.z, vf.w};
            float pa[4];
            #pragma unroll
            for (int i = 0; i < 4; i++) pa[i] = Ps[ty*4 + i][k];
            #pragma unroll
            for (int i = 0; i < 4; i++)
                #pragma unroll
                for (int j = 0; j < 4; j++)
                    o[i][j] += pa[i] * vb[j];
        }
    }

    // Finalize and write to [b*T+t][h*64+d].
    const int b_ = bh / HH, h = bh % HH;
    #pragma unroll
    for (int i = 0; i < 4; i++) {
        float inv = 1.0f / l_i[i];
        int t = qt*64 + ty*4 + i;
        float4 w = make_float4(o[i][0]*inv, o[i][1]*inv, o[i][2]*inv, o[i][3]*inv);
        *(float4*)&g_attn[((size_t)(b_*TT + t)) * DD + h*DHD + tx*4] = w;
    }
}

// ---------------------------------------------------------------------------
// Output projection: out = attn @ W_out + b_out   (8192 x 768 x 768)
// ---------------------------------------------------------------------------
__global__ void __launch_bounds__(256) out_gemm_kernel(
    const float* __restrict__ W, const float* __restrict__ bias,
    float* __restrict__ out)
{
    __shared__ float As[16][68];
    __shared__ float Bs[16][68];
    const int tid = threadIdx.x;
    const int tx = tid & 15, ty = tid >> 4;
    const int n0 = blockIdx.x * 64;
    const int m0 = blockIdx.y * 64;
    const int ar = tid >> 2, ac4 = tid & 3;
    const int br = tid >> 4, bc4 = tid & 15;

    float acc[4][4] = {};
    float4 av = *(const float4*)&g_attn[(size_t)(m0 + ar) * DD + ac4 * 4];
    float4 bv = *(const float4*)&W[(size_t)br * DD + n0 + bc4 * 4];

    for (int k0 = 0; k0 < DD; k0 += 16) {
        __syncthreads();
        As[ac4*4+0][ar] = av.x; As[ac4*4+1][ar] = av.y;
        As[ac4*4+2][ar] = av.z; As[ac4*4+3][ar] = av.w;
        *(float4*)&Bs[br][bc4*4] = bv;
        __syncthreads();
        if (k0 + 16 < DD) {
            av = *(const float4*)&g_attn[(size_t)(m0 + ar) * DD + (k0+16) + ac4 * 4];
            bv = *(const float4*)&W[(size_t)(k0+16 + br) * DD + n0 + bc4 * 4];
        }
        #pragma unroll
        for (int kk = 0; kk < 16; kk++) {
            float4 af = *(const float4*)&As[kk][ty*4];
            float4 bf = *(const float4*)&Bs[kk][tx*4];
            float a[4] = {af.x, af.y, af.z, af.w};
            float b[4] = {bf.x, bf.y, bf.z, bf.w};
            #pragma unroll
            for (int i = 0; i < 4; i++)
                #pragma unroll
                for (int j = 0; j < 4; j++)
                    acc[i][j] += a[i] * b[j];
        }
    }
    #pragma unroll
    for (int i = 0; i < 4; i++) {
        int m = m0 + ty*4 + i;
        int n = n0 + tx*4;
        float4 w = make_float4(acc[i][0] + bias[n+0], acc[i][1] + bias[n+1],
                               acc[i][2] + bias[n+2], acc[i][3] + bias[n+3]);
        *(float4*)&out[(size_t)m * DD + n] = w;
    }
}

// ---------------------------------------------------------------------------
extern "C" void kernel_launch(void* const* d_in, const int* in_sizes, int n_in,
                              void* d_out, int out_size)
{
    const float* x     = (const float*)d_in[0];
    const float* W_qkv = (const float*)d_in[1];
    const float* b_qkv = (const float*)d_in[2];
    const float* W_out = (const float*)d_in[3];
    const float* b_out = (const float*)d_in[4];
    float* out = (float*)d_out;

    (void)in_sizes; (void)n_in; (void)out_size;

    cudaFuncSetAttribute(attn_kernel,
                         cudaFuncAttributeMaxDynamicSharedMemorySize, ATTN_SMEM);

    qkv_gemm_kernel<<<dim3(NQKV/64, MTOT/64), 256>>>(x, W_qkv, b_qkv);
    attn_kernel<<<dim3(TT/64, BB*HH), 256, ATTN_SMEM>>>();
    out_gemm_kernel<<<dim3(DD/64, MTOT/64), 256>>>(W_out, b_out, out);
}